// round 4
// baseline (speedup 1.0000x reference)
#include <cuda_runtime.h>
#include <cuda_fp16.h>

#define N_USERS 100000
#define N_ITEMS 200000
#define N_NODES (N_USERS + N_ITEMS)
#define NNZ 6400000
#define H2_PER_NODE 32                      // 64 dims = 32 half2
#define BUF_H2 (N_NODES * H2_PER_NODE)      // 9.6M half2 = 38.4 MB
#define SCAN_BLK 1024
#define N_SCAN_BLOCKS ((N_NODES + SCAN_BLK - 1) / SCAN_BLK)   // 293

// Static device scratch. g_x[0]=x0, [1]=x1, [2]=x2, [3]=x3 (fp16).
__device__ __half2 g_x[4][BUF_H2];           // 4 x 38.4 MB
__device__ float2  g_cv[NNZ];                // packed {col_bits, val}
__device__ int     g_rowptr[N_NODES + 1];
__device__ int     g_cursor[N_NODES];
__device__ int     g_deg[N_NODES];
__device__ int     g_bsum[SCAN_BLK];

// ---------------- init: g_x[0] = fp16(concat(user,item)) ----------------
__global__ void init_kernel(const float2* __restrict__ user,
                            const float2* __restrict__ item) {
    int i = blockIdx.x * blockDim.x + threadIdx.x;
    if (i >= BUF_H2) return;
    const int uend = N_USERS * H2_PER_NODE;
    float2 v = (i < uend) ? __ldcs(&user[i]) : __ldcs(&item[i - uend]);
    g_x[0][i] = __float22half2_rn(v);
}

// ---------------- CSR build ----------------
__global__ void hist_kernel(const int* __restrict__ rows) {
    int e = blockIdx.x * blockDim.x + threadIdx.x;
    if (e < NNZ) atomicAdd(&g_deg[__ldcs(&rows[e])], 1);
}

__global__ void scan1_kernel() {
    __shared__ int s[SCAN_BLK];
    int t = threadIdx.x;
    int i = blockIdx.x * SCAN_BLK + t;
    int v = (i < N_NODES) ? g_deg[i] : 0;
    s[t] = v;
    __syncthreads();
    for (int off = 1; off < SCAN_BLK; off <<= 1) {
        int add = (t >= off) ? s[t - off] : 0;
        __syncthreads();
        s[t] += add;
        __syncthreads();
    }
    int incl = s[t];
    if (i < N_NODES) g_rowptr[i] = incl - v;
    if (t == SCAN_BLK - 1) g_bsum[blockIdx.x] = incl;
}

__global__ void scan2_kernel() {
    __shared__ int s[512];
    int t = threadIdx.x;
    int v = (t < N_SCAN_BLOCKS) ? g_bsum[t] : 0;
    s[t] = v;
    __syncthreads();
    for (int off = 1; off < 512; off <<= 1) {
        int add = (t >= off) ? s[t - off] : 0;
        __syncthreads();
        s[t] += add;
        __syncthreads();
    }
    if (t < N_SCAN_BLOCKS) g_bsum[t] = s[t] - v;
}

__global__ void scan3_kernel() {
    int i = blockIdx.x * blockDim.x + threadIdx.x;
    if (i >= N_NODES) return;
    int rp = g_rowptr[i] + g_bsum[i >> 10];
    g_rowptr[i] = rp;
    g_cursor[i] = rp;
    if (i == 0) g_rowptr[N_NODES] = NNZ;
}

__global__ void scatter_kernel(const int* __restrict__ rows,
                               const int* __restrict__ cols,
                               const float* __restrict__ vals) {
    int e = blockIdx.x * blockDim.x + threadIdx.x;
    if (e >= NNZ) return;
    int r = __ldcs(&rows[e]);
    int c = __ldcs(&cols[e]);
    float v = __ldcs(&vals[e]);
    int pos = atomicAdd(&g_cursor[r], 1);
    __stcs(&g_cv[pos], make_float2(__int_as_float(c), v));
}

// ---------------- CSR SpMM: warp per row, fp16 buffers, fp32 accum ----------------
// cv is streamed (__ldcs, evict-first) so the two active x buffers stay L2-resident.
__global__ void spmm_csr_kernel(int srcsel, int dstsel) {
    int gtid = blockIdx.x * blockDim.x + threadIdx.x;
    int row = gtid >> 5;
    int lane = threadIdx.x & 31;
    if (row >= N_NODES) return;

    const __half2* __restrict__ x = g_x[srcsel];
    __half2* __restrict__ y       = g_x[dstsel];

    int start = g_rowptr[row];
    int end   = g_rowptr[row + 1];

    float2 sum0 = make_float2(0.f, 0.f);
    float2 sum1 = make_float2(0.f, 0.f);

    for (int k = start; k < end; k += 32) {
        int myk = k + lane;
        float2 cv = (myk < end) ? __ldcs(&g_cv[myk]) : make_float2(0.f, 0.f);
        int cnt = min(32, end - k);

        int j = 0;
        // pairs of edges -> two independent load+fma chains
        #pragma unroll 4
        for (; j + 2 <= cnt; j += 2) {
            int   c0 = __shfl_sync(0xffffffffu, __float_as_int(cv.x), j);
            float v0 = __shfl_sync(0xffffffffu, cv.y, j);
            int   c1 = __shfl_sync(0xffffffffu, __float_as_int(cv.x), j + 1);
            float v1 = __shfl_sync(0xffffffffu, cv.y, j + 1);
            float2 x0 = __half22float2(__ldg(&x[c0 * H2_PER_NODE + lane]));
            float2 x1 = __half22float2(__ldg(&x[c1 * H2_PER_NODE + lane]));
            sum0.x = fmaf(v0, x0.x, sum0.x);
            sum0.y = fmaf(v0, x0.y, sum0.y);
            sum1.x = fmaf(v1, x1.x, sum1.x);
            sum1.y = fmaf(v1, x1.y, sum1.y);
        }
        if (j < cnt) {
            int   c0 = __shfl_sync(0xffffffffu, __float_as_int(cv.x), j);
            float v0 = __shfl_sync(0xffffffffu, cv.y, j);
            float2 x0 = __half22float2(__ldg(&x[c0 * H2_PER_NODE + lane]));
            sum0.x = fmaf(v0, x0.x, sum0.x);
            sum0.y = fmaf(v0, x0.y, sum0.y);
        }
    }
    sum0.x += sum1.x;
    sum0.y += sum1.y;
    y[row * H2_PER_NODE + lane] = __float22half2_rn(sum0);
}

// ---------------- final: out = (x0_fp32 + x1 + x2 + x3) / 4 ----------------
__global__ void final_kernel(const float2* __restrict__ user,
                             const float2* __restrict__ item,
                             float2* __restrict__ out) {
    int i = blockIdx.x * blockDim.x + threadIdx.x;
    if (i >= BUF_H2) return;
    const int uend = N_USERS * H2_PER_NODE;
    float2 a = (i < uend) ? __ldcs(&user[i]) : __ldcs(&item[i - uend]);
    float2 x1 = __half22float2(__ldcs(&g_x[1][i]));
    float2 x2 = __half22float2(__ldcs(&g_x[2][i]));
    float2 x3 = __half22float2(__ldcs(&g_x[3][i]));
    a.x = (a.x + x1.x + x2.x + x3.x) * 0.25f;
    a.y = (a.y + x1.y + x2.y + x3.y) * 0.25f;
    __stcs(&out[i], a);
}

extern "C" void kernel_launch(void* const* d_in, const int* in_sizes, int n_in,
                              void* d_out, int out_size) {
    const float2* user = (const float2*)d_in[0];
    const float2* item = (const float2*)d_in[1];
    const int*   rows  = (const int*)d_in[2];
    const int*   cols  = (const int*)d_in[3];
    const float* vals  = (const float*)d_in[4];
    float2* out = (float2*)d_out;

    const int BLK = 256;
    const int gridBuf  = (BUF_H2 + BLK - 1) / BLK;
    const int gridNode = (N_NODES + BLK - 1) / BLK;
    const int gridEdge = (NNZ + BLK - 1) / BLK;
    const int gridSpmm = (N_NODES * 32 + BLK - 1) / BLK;   // warp per row

    init_kernel<<<gridBuf, BLK>>>(user, item);

    // CSR build
    int* d_deg = nullptr;
    cudaGetSymbolAddress((void**)&d_deg, g_deg);
    cudaMemsetAsync(d_deg, 0, N_NODES * sizeof(int));
    hist_kernel<<<gridEdge, BLK>>>(rows);
    scan1_kernel<<<N_SCAN_BLOCKS, SCAN_BLK>>>();
    scan2_kernel<<<1, 512>>>();
    scan3_kernel<<<gridNode, BLK>>>();
    scatter_kernel<<<gridEdge, BLK>>>(rows, cols, vals);

    // 3 propagation layers (write-only outputs)
    spmm_csr_kernel<<<gridSpmm, BLK>>>(0, 1);   // x1 = A @ x0
    spmm_csr_kernel<<<gridSpmm, BLK>>>(1, 2);   // x2 = A @ x1
    spmm_csr_kernel<<<gridSpmm, BLK>>>(2, 3);   // x3 = A @ x2

    final_kernel<<<gridBuf, BLK>>>(user, item, out);
}

// round 5
// speedup vs baseline: 1.2638x; 1.2638x over previous
#include <cuda_runtime.h>
#include <cuda_fp16.h>

#define N_USERS 100000
#define N_ITEMS 200000
#define N_NODES (N_USERS + N_ITEMS)
#define NNZ 6400000
#define H2_PER_NODE 32                      // 64 dims = 32 half2
#define U2_PER_NODE 16                      // 64 dims = 16 uint2 (4 half each)
#define BUF_H2 (N_NODES * H2_PER_NODE)      // 9.6M half2 = 38.4 MB
#define SCAN_BLK 1024
#define N_SCAN_BLOCKS ((N_NODES + SCAN_BLK - 1) / SCAN_BLK)   // 293

// Static device scratch. g_x[0]=x0, [1]=x1, [2]=x2, [3]=x3 (fp16).
__device__ __half2 g_x[4][BUF_H2];           // 4 x 38.4 MB
__device__ float2  g_cv[NNZ];                // packed {col_bits, val}
__device__ int     g_rowptr[N_NODES + 1];
__device__ int     g_cursor[N_NODES];
__device__ int     g_deg[N_NODES];
__device__ int     g_bsum[SCAN_BLK];

// ---------------- init: g_x[0] = fp16(concat(user,item)) ----------------
__global__ void init_kernel(const float2* __restrict__ user,
                            const float2* __restrict__ item) {
    int i = blockIdx.x * blockDim.x + threadIdx.x;
    if (i >= BUF_H2) return;
    const int uend = N_USERS * H2_PER_NODE;
    float2 v = (i < uend) ? user[i] : item[i - uend];
    g_x[0][i] = __float22half2_rn(v);
}

// ---------------- CSR build ----------------
__global__ void hist_kernel(const int* __restrict__ rows) {
    int e = blockIdx.x * blockDim.x + threadIdx.x;
    if (e < NNZ) atomicAdd(&g_deg[rows[e]], 1);
}

__global__ void scan1_kernel() {
    __shared__ int s[SCAN_BLK];
    int t = threadIdx.x;
    int i = blockIdx.x * SCAN_BLK + t;
    int v = (i < N_NODES) ? g_deg[i] : 0;
    s[t] = v;
    __syncthreads();
    for (int off = 1; off < SCAN_BLK; off <<= 1) {
        int add = (t >= off) ? s[t - off] : 0;
        __syncthreads();
        s[t] += add;
        __syncthreads();
    }
    int incl = s[t];
    if (i < N_NODES) g_rowptr[i] = incl - v;
    if (t == SCAN_BLK - 1) g_bsum[blockIdx.x] = incl;
}

__global__ void scan2_kernel() {
    __shared__ int s[512];
    int t = threadIdx.x;
    int v = (t < N_SCAN_BLOCKS) ? g_bsum[t] : 0;
    s[t] = v;
    __syncthreads();
    for (int off = 1; off < 512; off <<= 1) {
        int add = (t >= off) ? s[t - off] : 0;
        __syncthreads();
        s[t] += add;
        __syncthreads();
    }
    if (t < N_SCAN_BLOCKS) g_bsum[t] = s[t] - v;
}

__global__ void scan3_kernel() {
    int i = blockIdx.x * blockDim.x + threadIdx.x;
    if (i >= N_NODES) return;
    int rp = g_rowptr[i] + g_bsum[i >> 10];
    g_rowptr[i] = rp;
    g_cursor[i] = rp;
    if (i == 0) g_rowptr[N_NODES] = NNZ;
}

__global__ void scatter_kernel(const int* __restrict__ rows,
                               const int* __restrict__ cols,
                               const float* __restrict__ vals) {
    int e = blockIdx.x * blockDim.x + threadIdx.x;
    if (e >= NNZ) return;
    int r = rows[e];
    int pos = atomicAdd(&g_cursor[r], 1);
    g_cv[pos] = make_float2(__int_as_float(cols[e]), vals[e]);
}

// ---------------- CSR SpMM: warp per row, 16 lanes x uint2, 2 edges/step ------
// Half-warp h processes edges with index parity h within each 32-edge batch.
// Lane covers dims [4*hl, 4*hl+4) as one uint2 (2 half2). fp32 accumulation.
__global__ void spmm_csr_kernel(int srcsel, int dstsel) {
    int gtid = blockIdx.x * blockDim.x + threadIdx.x;
    int row = gtid >> 5;
    int lane = threadIdx.x & 31;
    if (row >= N_NODES) return;

    int half = lane >> 4;       // 0 or 1
    int hl   = lane & 15;       // lane within half-warp

    const uint2* __restrict__ x = (const uint2*)g_x[srcsel];
    uint2* __restrict__ y       = (uint2*)g_x[dstsel];

    int start = g_rowptr[row];
    int end   = g_rowptr[row + 1];

    float4 acc = make_float4(0.f, 0.f, 0.f, 0.f);

    for (int k = start; k < end; k += 32) {
        int myk = k + lane;
        // zero-fill => col 0, val 0: contributes nothing, loads stay valid
        float2 cv = (myk < end) ? g_cv[myk] : make_float2(0.f, 0.f);
        int cnt  = min(32, end - k);
        int jmax = (cnt + 1) >> 1;          // uniform across warp

        #pragma unroll 4
        for (int j = 0; j < jmax; j++) {
            int e = 2 * j + half;           // this half-warp's edge slot
            int   cj = __shfl_sync(0xffffffffu, __float_as_int(cv.x), e);
            float vj = __shfl_sync(0xffffffffu, cv.y, e);
            uint2 xr = __ldg(&x[cj * U2_PER_NODE + hl]);
            float2 a = __half22float2(*(const __half2*)&xr.x);
            float2 b = __half22float2(*(const __half2*)&xr.y);
            acc.x = fmaf(vj, a.x, acc.x);
            acc.y = fmaf(vj, a.y, acc.y);
            acc.z = fmaf(vj, b.x, acc.z);
            acc.w = fmaf(vj, b.y, acc.w);
        }
    }

    // combine the two half-warps' partial sums (same dims, different edges)
    acc.x += __shfl_xor_sync(0xffffffffu, acc.x, 16);
    acc.y += __shfl_xor_sync(0xffffffffu, acc.y, 16);
    acc.z += __shfl_xor_sync(0xffffffffu, acc.z, 16);
    acc.w += __shfl_xor_sync(0xffffffffu, acc.w, 16);

    if (half == 0) {
        uint2 o;
        __half2 lo = __float22half2_rn(make_float2(acc.x, acc.y));
        __half2 hi = __float22half2_rn(make_float2(acc.z, acc.w));
        o.x = *(const unsigned int*)&lo;
        o.y = *(const unsigned int*)&hi;
        y[row * U2_PER_NODE + hl] = o;
    }
}

// ---------------- final: out = (x0_fp32 + x1 + x2 + x3) / 4 ----------------
__global__ void final_kernel(const float2* __restrict__ user,
                             const float2* __restrict__ item,
                             float2* __restrict__ out) {
    int i = blockIdx.x * blockDim.x + threadIdx.x;
    if (i >= BUF_H2) return;
    const int uend = N_USERS * H2_PER_NODE;
    float2 a = (i < uend) ? user[i] : item[i - uend];
    float2 x1 = __half22float2(g_x[1][i]);
    float2 x2 = __half22float2(g_x[2][i]);
    float2 x3 = __half22float2(g_x[3][i]);
    a.x = (a.x + x1.x + x2.x + x3.x) * 0.25f;
    a.y = (a.y + x1.y + x2.y + x3.y) * 0.25f;
    out[i] = a;
}

extern "C" void kernel_launch(void* const* d_in, const int* in_sizes, int n_in,
                              void* d_out, int out_size) {
    const float2* user = (const float2*)d_in[0];
    const float2* item = (const float2*)d_in[1];
    const int*   rows  = (const int*)d_in[2];
    const int*   cols  = (const int*)d_in[3];
    const float* vals  = (const float*)d_in[4];
    float2* out = (float2*)d_out;

    const int BLK = 256;
    const int gridBuf  = (BUF_H2 + BLK - 1) / BLK;
    const int gridNode = (N_NODES + BLK - 1) / BLK;
    const int gridEdge = (NNZ + BLK - 1) / BLK;
    const int gridSpmm = (N_NODES * 32 + BLK - 1) / BLK;   // warp per row

    init_kernel<<<gridBuf, BLK>>>(user, item);

    // CSR build
    int* d_deg = nullptr;
    cudaGetSymbolAddress((void**)&d_deg, g_deg);
    cudaMemsetAsync(d_deg, 0, N_NODES * sizeof(int));
    hist_kernel<<<gridEdge, BLK>>>(rows);
    scan1_kernel<<<N_SCAN_BLOCKS, SCAN_BLK>>>();
    scan2_kernel<<<1, 512>>>();
    scan3_kernel<<<gridNode, BLK>>>();
    scatter_kernel<<<gridEdge, BLK>>>(rows, cols, vals);

    // 3 propagation layers (write-only outputs)
    spmm_csr_kernel<<<gridSpmm, BLK>>>(0, 1);   // x1 = A @ x0
    spmm_csr_kernel<<<gridSpmm, BLK>>>(1, 2);   // x2 = A @ x1
    spmm_csr_kernel<<<gridSpmm, BLK>>>(2, 3);   // x3 = A @ x2

    final_kernel<<<gridBuf, BLK>>>(user, item, out);
}